// round 5
// baseline (speedup 1.0000x reference)
#include <cuda_runtime.h>
#include <cstdint>

#define NTHR 256
#define KTOT 1152
#define NCH  36          // K chunks of 32

// smem layout (bytes) — 78,336 total -> 2 CTAs/SM
#define A_ROWB 144       // 128B data + 16B pad (conflict-free ldmatrix)
#define B_ROWB 144
#define SM_A0  0                       // 128 rows * 144
#define SM_A1  18432
#define SM_B0  36864                   // 128 rows * 144
#define SM_B1  55296
#define SM_OFF 73728                   // 1152 int offsets
#define SM_TOT 78336
#define EPI_LD 132                     // epilogue [128 oc][132 m] floats (67.6KB, fits)

// ---- tf32-preconverted scratch (device globals: allowed scratch) ----
__device__ float g_in_tf[32u * 128u * 64u * 64u];   // 67.1 MB
__device__ float g_wt_tf[256u * KTOT];              // 1.18 MB

__device__ __forceinline__ uint32_t s2u(const void* p) {
    uint32_t a;
    asm("{ .reg .u64 t; cvta.to.shared.u64 t, %1; cvt.u32.u64 %0, t; }" : "=r"(a) : "l"(p));
    return a;
}

__device__ __forceinline__ void ldsm4(uint32_t* r, uint32_t addr) {
    asm volatile("ldmatrix.sync.aligned.m8n8.x4.shared.b16 {%0,%1,%2,%3}, [%4];"
        : "=r"(r[0]), "=r"(r[1]), "=r"(r[2]), "=r"(r[3]) : "r"(addr));
}

__device__ __forceinline__ float f2tf(float f) {
    uint32_t o;
    asm("cvt.rna.tf32.f32 %0, %1;" : "=r"(o) : "f"(f));
    return __uint_as_float(o);
}

__device__ __forceinline__ void mma8(float* d, const uint32_t* a, const uint32_t* b) {
    asm volatile("mma.sync.aligned.m16n8k8.row.col.f32.tf32.tf32.f32 "
        "{%0,%1,%2,%3}, {%4,%5,%6,%7}, {%8,%9}, {%0,%1,%2,%3};"
        : "+f"(d[0]), "+f"(d[1]), "+f"(d[2]), "+f"(d[3])
        : "r"(a[0]), "r"(a[1]), "r"(a[2]), "r"(a[3]), "r"(b[0]), "r"(b[1]));
}

#define CP4(dst, src) \
    asm volatile("cp.async.ca.shared.global [%0], [%1], 4;"  :: "r"(dst), "l"(src) : "memory")
#define CP16(dst, src) \
    asm volatile("cp.async.cg.shared.global [%0], [%1], 16;" :: "r"(dst), "l"(src) : "memory")
#define CP_COMMIT() asm volatile("cp.async.commit_group;" ::: "memory")

// ---- prepass: f32 -> tf32 bit patterns, vectorized ----
__global__ __launch_bounds__(256) void cvt_in_kernel(const float4* __restrict__ src) {
    float4* dst = reinterpret_cast<float4*>(g_in_tf);
    const int n4 = (32 * 128 * 64 * 64) / 4;
    for (int i = blockIdx.x * blockDim.x + threadIdx.x; i < n4; i += gridDim.x * blockDim.x) {
        float4 v = src[i];
        v.x = f2tf(v.x); v.y = f2tf(v.y); v.z = f2tf(v.z); v.w = f2tf(v.w);
        dst[i] = v;
    }
}
__global__ __launch_bounds__(256) void cvt_wt_kernel(const float4* __restrict__ src) {
    float4* dst = reinterpret_cast<float4*>(g_wt_tf);
    const int n4 = (256 * KTOT) / 4;
    for (int i = blockIdx.x * blockDim.x + threadIdx.x; i < n4; i += gridDim.x * blockDim.x) {
        float4 v = src[i];
        v.x = f2tf(v.x); v.y = f2tf(v.y); v.z = f2tf(v.z); v.w = f2tf(v.w);
        dst[i] = v;
    }
}

__global__ __launch_bounds__(NTHR, 2)
void conv2d_tf32_mmasync(float* __restrict__ out)
{
    extern __shared__ char smem[];
    const uint32_t sb = s2u(smem);
    float* smf = (float*)smem;
    int* offs = (int*)(smem + SM_OFF);

    const int tid = threadIdx.x;
    const int wid = tid >> 5, lane = tid & 31;
    const int n   = blockIdx.y;
    const int oh0 = blockIdx.x * 2;
    const int zoc = blockIdx.z * 128;              // oc half

    // k -> input offset table (floats): ic*4096 + kh*64 + kw
    for (int k = tid; k < KTOT; k += NTHR) {
        int ic = k / 9, t9 = k - ic * 9;
        int kh = t9 / 3, kw = t9 - kh * 3;
        offs[k] = ic * 4096 + kh * 64 + kw;
    }

    // A staging: m row = tid & 127, two k-phases (tid>>7), 16 CP4 each
    const float* in_n = g_in_tf + (size_t)n * 128 * 64 * 64;
    const float* wt   = g_wt_tf + (size_t)zoc * KTOT;
    const int am = tid & 127, aib = tid >> 7;              // aib in 0..1
    const int aow = am & 63;
    const float* abase = in_n + (size_t)(oh0 + (am >> 6)) * 64 + (aow < 62 ? aow : 0);
    const int bq = tid & 7, bocb = tid >> 3;               // bocb in 0..31

    // warp tiling: 4x2 grid, warp tile m32 x n64
    const int m0 = (wid & 3) * 32, n0 = (wid >> 2) * 64;
    const int T = lane >> 3, rowin = lane & 7;
    uint32_t aoff[2], boff[4];
    #pragma unroll
    for (int mi = 0; mi < 2; mi++) {
        int r = m0 + mi * 16 + ((T & 1) << 3) + rowin;
        aoff[mi] = r * A_ROWB + ((T >> 1) << 4);
    }
    #pragma unroll
    for (int nb = 0; nb < 4; nb++) {
        int r = n0 + nb * 16 + ((T >> 1) << 3) + rowin;
        boff[nb] = r * B_ROWB + ((T & 1) << 4);
    }

    float acc[2][8][4];
    #pragma unroll
    for (int i = 0; i < 2; i++)
        #pragma unroll
        for (int j = 0; j < 8; j++)
            #pragma unroll
            for (int v = 0; v < 4; v++) acc[i][j][v] = 0.0f;

    __syncthreads();   // offs table ready

    // ---- stage chunk 0 ----
    {
        uint32_t As = sb + SM_A0, Bs = sb + SM_B0;
        #pragma unroll
        for (int i = 0; i < 16; i++) {
            int kk = i * 2 + aib;
            CP4(As + am * A_ROWB + kk * 4, abase + offs[kk]);
        }
        #pragma unroll
        for (int j = 0; j < 4; j++) {
            int oc = j * 32 + bocb;
            CP16(Bs + oc * B_ROWB + bq * 16, wt + (size_t)oc * KTOT + bq * 4);
        }
        CP_COMMIT();
    }

    #pragma unroll 1
    for (int kc = 0; kc < NCH; kc++) {
        if (kc + 1 < NCH) {   // stage next chunk into other buffer
            uint32_t As = sb + (((kc + 1) & 1) ? SM_A1 : SM_A0);
            uint32_t Bs = sb + (((kc + 1) & 1) ? SM_B1 : SM_B0);
            #pragma unroll
            for (int i = 0; i < 16; i++) {
                int kk = i * 2 + aib;
                CP4(As + am * A_ROWB + kk * 4, abase + offs[(kc + 1) * 32 + kk]);
            }
            #pragma unroll
            for (int j = 0; j < 4; j++) {
                int oc = j * 32 + bocb;
                CP16(Bs + oc * B_ROWB + bq * 16,
                     wt + (size_t)oc * KTOT + (kc + 1) * 32 + bq * 4);
            }
            CP_COMMIT();
            asm volatile("cp.async.wait_group 1;" ::: "memory");
        } else {
            asm volatile("cp.async.wait_group 0;" ::: "memory");
        }
        __syncthreads();   // chunk kc visible to all

        // ---- compute chunk kc: pure ldmatrix + mma ----
        uint32_t As = sb + ((kc & 1) ? SM_A1 : SM_A0);
        uint32_t Bs = sb + ((kc & 1) ? SM_B1 : SM_B0);
        #pragma unroll
        for (int s = 0; s < 4; s++) {
            uint32_t a[2][4], b[4][4];
            #pragma unroll
            for (int mi = 0; mi < 2; mi++)
                ldsm4(a[mi], As + aoff[mi] + s * 32);
            #pragma unroll
            for (int nb = 0; nb < 4; nb++)
                ldsm4(b[nb], Bs + boff[nb] + s * 32);
            #pragma unroll
            for (int mi = 0; mi < 2; mi++)
                #pragma unroll
                for (int nb = 0; nb < 4; nb++) {
                    mma8(acc[mi][2 * nb],     a[mi], &b[nb][0]);
                    mma8(acc[mi][2 * nb + 1], a[mi], &b[nb][2]);
                }
        }
        __syncthreads();   // compute done before buffer reuse
    }

    // ---- epilogue: smem transpose to [oc][m], coalesced stores ----
    const int eg = lane >> 2, ee = lane & 3;
    #pragma unroll
    for (int mi = 0; mi < 2; mi++)
        #pragma unroll
        for (int nj = 0; nj < 8; nj++) {
            int ocl = n0 + nj * 8 + 2 * ee;
            int mm  = m0 + mi * 16 + eg;
            smf[ocl * EPI_LD + mm]           = acc[mi][nj][0];
            smf[(ocl + 1) * EPI_LD + mm]     = acc[mi][nj][1];
            smf[ocl * EPI_LD + mm + 8]       = acc[mi][nj][2];
            smf[(ocl + 1) * EPI_LD + mm + 8] = acc[mi][nj][3];
        }
    __syncthreads();
    #pragma unroll 8
    for (int i = 0; i < 64; i++) {
        int idx = i * NTHR + tid;
        int mm = idx & 127, ocl = idx >> 7;
        int ow = mm & 63, oh = oh0 + (mm >> 6);
        if (ow < 62)
            out[((size_t)n * 256 + zoc + ocl) * 3844 + (size_t)oh * 62 + ow]
                = smf[ocl * EPI_LD + mm];
    }
}

extern "C" void kernel_launch(void* const* d_in, const int* in_sizes, int n_in,
                              void* d_out, int out_size)
{
    const float* in = (const float*)d_in[0];   // [32,128,64,64]
    const float* wt = (const float*)d_in[1];   // [256,128,3,3]
    float* out = (float*)d_out;                // [32,256,62,62]

    // prepass: convert input + weights to tf32 bit patterns
    cvt_in_kernel<<<2048, 256>>>(reinterpret_cast<const float4*>(in));
    cvt_wt_kernel<<<288, 256>>>(reinterpret_cast<const float4*>(wt));

    cudaFuncSetAttribute(conv2d_tf32_mmasync,
                         cudaFuncAttributeMaxDynamicSharedMemorySize, SM_TOT);
    dim3 grid(31, 32, 2);
    conv2d_tf32_mmasync<<<grid, NTHR, SM_TOT>>>(out);
}

// round 6
// speedup vs baseline: 1.4647x; 1.4647x over previous
#include <cuda_runtime.h>
#include <cstdint>

#define NTHR 512
#define KTOT 1152
#define NCH  36          // K chunks of 32

// smem layout (bytes) — swizzled 128B rows, no padding
#define SM_A0  0                       // 128 rows * 128B = 16KB
#define SM_A1  16384
#define SM_B0  32768                   // 256 rows * 128B = 32KB
#define SM_B1  65536
#define SM_OFF 98304                   // 1152 int offsets
#define SM_TOT 103040
#define EPI_LD 132                     // epilogue [128 oc][132 m] floats

// ---- tf32-preconverted scratch (device globals: allowed scratch) ----
__device__ float g_in_tf[32u * 128u * 64u * 64u];   // 67.1 MB
__device__ float g_wt_tf[256u * KTOT];              // 1.18 MB

__device__ __forceinline__ uint32_t s2u(const void* p) {
    uint32_t a;
    asm("{ .reg .u64 t; cvta.to.shared.u64 t, %1; cvt.u32.u64 %0, t; }" : "=r"(a) : "l"(p));
    return a;
}

__device__ __forceinline__ void ldsm4(uint32_t* r, uint32_t addr) {
    asm volatile("ldmatrix.sync.aligned.m8n8.x4.shared.b16 {%0,%1,%2,%3}, [%4];"
        : "=r"(r[0]), "=r"(r[1]), "=r"(r[2]), "=r"(r[3]) : "r"(addr));
}

__device__ __forceinline__ float f2tf(float f) {
    uint32_t o;
    asm("cvt.rna.tf32.f32 %0, %1;" : "=r"(o) : "f"(f));
    return __uint_as_float(o);
}

__device__ __forceinline__ void mma8(float* d, const uint32_t* a, const uint32_t* b) {
    asm volatile("mma.sync.aligned.m16n8k8.row.col.f32.tf32.tf32.f32 "
        "{%0,%1,%2,%3}, {%4,%5,%6,%7}, {%8,%9}, {%0,%1,%2,%3};"
        : "+f"(d[0]), "+f"(d[1]), "+f"(d[2]), "+f"(d[3])
        : "r"(a[0]), "r"(a[1]), "r"(a[2]), "r"(a[3]), "r"(b[0]), "r"(b[1]));
}

#define CP16(dst, src) \
    asm volatile("cp.async.cg.shared.global [%0], [%1], 16;" :: "r"(dst), "l"(src) : "memory")
#define CP_COMMIT()  asm volatile("cp.async.commit_group;" ::: "memory")
#define CP_WAIT0()   asm volatile("cp.async.wait_group 0;" ::: "memory")
#define STS128(a, r) \
    asm volatile("st.shared.v4.b32 [%0], {%1,%2,%3,%4};" :: "r"(a), \
        "r"(__float_as_uint((r)[0])), "r"(__float_as_uint((r)[1])), \
        "r"(__float_as_uint((r)[2])), "r"(__float_as_uint((r)[3])) : "memory")

// ---- prepass: f32 -> tf32 bit patterns, vectorized ----
__global__ __launch_bounds__(256) void cvt_in_kernel(const float4* __restrict__ src) {
    float4* dst = reinterpret_cast<float4*>(g_in_tf);
    const int n4 = (32 * 128 * 64 * 64) / 4;
    for (int i = blockIdx.x * blockDim.x + threadIdx.x; i < n4; i += gridDim.x * blockDim.x) {
        float4 v = src[i];
        v.x = f2tf(v.x); v.y = f2tf(v.y); v.z = f2tf(v.z); v.w = f2tf(v.w);
        dst[i] = v;
    }
}
__global__ __launch_bounds__(256) void cvt_wt_kernel(const float4* __restrict__ src) {
    float4* dst = reinterpret_cast<float4*>(g_wt_tf);
    const int n4 = (256 * KTOT) / 4;
    for (int i = blockIdx.x * blockDim.x + threadIdx.x; i < n4; i += gridDim.x * blockDim.x) {
        float4 v = src[i];
        v.x = f2tf(v.x); v.y = f2tf(v.y); v.z = f2tf(v.z); v.w = f2tf(v.w);
        dst[i] = v;
    }
}

__global__ __launch_bounds__(NTHR, 1)
void conv2d_tf32_mmasync(float* __restrict__ out)
{
    extern __shared__ char smem[];
    const uint32_t sb = s2u(smem);
    float* smf = (float*)smem;
    int* offs = (int*)(smem + SM_OFF);

    const int tid = threadIdx.x;
    const int wid = tid >> 5, lane = tid & 31;
    const int n   = blockIdx.y;
    const int oh0 = blockIdx.x * 2;

    // k -> input offset table (floats): ic*4096 + kh*64 + kw
    for (int k = tid; k < KTOT; k += NTHR) {
        int ic = k / 9, t9 = k - ic * 9;
        int kh = t9 / 3, kw = t9 - kh * 3;
        offs[k] = ic * 4096 + kh * 64 + kw;
    }

    // ---- A staging: thread = (m = tid&127, k-octet aq = tid>>7) ----
    const float* in_n = g_in_tf + (size_t)n * 128 * 64 * 64;
    const float* wtp  = g_wt_tf;
    const int am = tid & 127, aq = tid >> 7;          // aq in 0..3
    const int aow = am & 63;
    const float* abase = in_n + (size_t)(oh0 + (am >> 6)) * 64 + (aow < 62 ? aow : 0);
    const uint32_t axm_st  = (uint32_t)(am & 7) << 4;
    const uint32_t asts0 = (uint32_t)am * 128 + (((uint32_t)aq * 32)      ^ axm_st);
    const uint32_t asts1 = (uint32_t)am * 128 + (((uint32_t)aq * 32 + 16) ^ axm_st);

    // ---- B staging: thread = (oc-block bocb = tid>>3, quad bq = tid&7) ----
    const int bq = tid & 7, bocb = tid >> 3;          // bocb in 0..63
    const uint32_t bstcol = ((uint32_t)bq * 16) ^ ((uint32_t)(bocb & 7) << 4);

    // ---- warp tiling: 4x4 grid, warp tile m32 x n64 ----
    const int m0 = (wid & 3) * 32, n0 = (wid >> 2) * 64;
    const int T = lane >> 3, rowin = lane & 7;
    const uint32_t acol = (uint32_t)(T >> 1) << 4;
    const uint32_t bcol = (uint32_t)(T & 1) << 4;
    uint32_t arow[2], axm[2], brow[4], bxm[4];
    #pragma unroll
    for (int mi = 0; mi < 2; mi++) {
        int r = m0 + mi * 16 + ((T & 1) << 3) + rowin;
        arow[mi] = (uint32_t)r * 128; axm[mi] = (uint32_t)(r & 7) << 4;
    }
    #pragma unroll
    for (int nb = 0; nb < 4; nb++) {
        int r = n0 + nb * 16 + ((T >> 1) << 3) + rowin;
        brow[nb] = (uint32_t)r * 128; bxm[nb] = (uint32_t)(r & 7) << 4;
    }

    float acc[2][8][4];
    #pragma unroll
    for (int i = 0; i < 2; i++)
        #pragma unroll
        for (int j = 0; j < 8; j++)
            #pragma unroll
            for (int v = 0; v < 4; v++) acc[i][j][v] = 0.0f;

    __syncthreads();   // offs table ready

    float ar[8];
    // ---- prologue: chunk 0 ----
    {
        const int kb = aq * 8;
        #pragma unroll
        for (int j = 0; j < 8; j++) ar[j] = abase[offs[kb + j]];
        const uint32_t Bs = sb + SM_B0;
        #pragma unroll
        for (int j = 0; j < 4; j++) {
            int oc = j * 64 + bocb;
            CP16(Bs + (uint32_t)oc * 128 + bstcol, wtp + (size_t)oc * KTOT + bq * 4);
        }
        CP_COMMIT();
        const uint32_t As = sb + SM_A0;
        STS128(As + asts0, ar);
        STS128(As + asts1, ar + 4);
        CP_WAIT0();
    }
    __syncthreads();

    #pragma unroll 1
    for (int kc = 0; kc < NCH; kc++) {
        const uint32_t As = sb + ((kc & 1) ? SM_A1 : SM_A0);
        const uint32_t Bs = sb + ((kc & 1) ? SM_B1 : SM_B0);
        const uint32_t An = sb + ((kc & 1) ? SM_A0 : SM_A1);
        const uint32_t Bn = sb + ((kc & 1) ? SM_B0 : SM_B1);

        if (kc + 1 < NCH) {   // issue next-chunk loads before compute
            const int kb = (kc + 1) * 32 + aq * 8;
            #pragma unroll
            for (int j = 0; j < 8; j++) ar[j] = abase[offs[kb + j]];
            #pragma unroll
            for (int j = 0; j < 4; j++) {
                int oc = j * 64 + bocb;
                CP16(Bn + (uint32_t)oc * 128 + bstcol,
                     wtp + (size_t)oc * KTOT + (kc + 1) * 32 + bq * 4);
            }
            CP_COMMIT();
        }

        // ---- compute chunk kc: pure ldmatrix + mma ----
        #pragma unroll
        for (int s = 0; s < 4; s++) {
            uint32_t a[2][4], b[4][4];
            #pragma unroll
            for (int mi = 0; mi < 2; mi++)
                ldsm4(a[mi], As + arow[mi] + ((acol | ((uint32_t)s << 5)) ^ axm[mi]));
            #pragma unroll
            for (int nb = 0; nb < 4; nb++)
                ldsm4(b[nb], Bs + brow[nb] + ((bcol | ((uint32_t)s << 5)) ^ bxm[nb]));
            #pragma unroll
            for (int mi = 0; mi < 2; mi++)
                #pragma unroll
                for (int nb = 0; nb < 4; nb++) {
                    mma8(acc[mi][2 * nb],     a[mi], &b[nb][0]);
                    mma8(acc[mi][2 * nb + 1], a[mi], &b[nb][2]);
                }
        }

        if (kc + 1 < NCH) {   // finish next-chunk staging
            STS128(An + asts0, ar);
            STS128(An + asts1, ar + 4);
            CP_WAIT0();
        }
        __syncthreads();      // single barrier per chunk
    }

    // ---- epilogue: smem transpose to [oc][m], coalesced stores ----
    const int eg = lane >> 2, ee = lane & 3;
    #pragma unroll 1
    for (int p = 0; p < 2; p++) {
        if ((n0 >> 7) == p) {
            #pragma unroll
            for (int mi = 0; mi < 2; mi++)
                #pragma unroll
                for (int nj = 0; nj < 8; nj++) {
                    int ocl = n0 - p * 128 + nj * 8 + 2 * ee;
                    int mm  = m0 + mi * 16 + eg;
                    smf[ocl * EPI_LD + mm]           = acc[mi][nj][0];
                    smf[(ocl + 1) * EPI_LD + mm]     = acc[mi][nj][1];
                    smf[ocl * EPI_LD + mm + 8]       = acc[mi][nj][2];
                    smf[(ocl + 1) * EPI_LD + mm + 8] = acc[mi][nj][3];
                }
        }
        __syncthreads();
        #pragma unroll 4
        for (int i = 0; i < 32; i++) {
            int idx = i * NTHR + tid;
            int mm = idx & 127, ocl = idx >> 7;
            int ow = mm & 63, oh = oh0 + (mm >> 6);
            if (ow < 62)
                out[((size_t)n * 256 + p * 128 + ocl) * 3844 + (size_t)oh * 62 + ow]
                    = smf[ocl * EPI_LD + mm];
        }
        __syncthreads();
    }
}

extern "C" void kernel_launch(void* const* d_in, const int* in_sizes, int n_in,
                              void* d_out, int out_size)
{
    const float* in = (const float*)d_in[0];   // [32,128,64,64]
    const float* wt = (const float*)d_in[1];   // [256,128,3,3]
    float* out = (float*)d_out;                // [32,256,62,62]

    // prepass: convert input + weights to tf32 bit patterns
    cvt_in_kernel<<<2048, 256>>>(reinterpret_cast<const float4*>(in));
    cvt_wt_kernel<<<288, 256>>>(reinterpret_cast<const float4*>(wt));

    cudaFuncSetAttribute(conv2d_tf32_mmasync,
                         cudaFuncAttributeMaxDynamicSharedMemorySize, SM_TOT);
    dim3 grid(31, 32);
    conv2d_tf32_mmasync<<<grid, NTHR, SM_TOT>>>(out);
}

// round 7
// speedup vs baseline: 1.4714x; 1.0046x over previous
#include <cuda_runtime.h>
#include <cstdint>

#define NTHR 256
#define KTOT 1152
#define NCH  36          // K chunks of 32

// smem layout (bytes) — swizzled 128B rows, no padding
#define SM_A0  0                       // 128 rows * 128B = 16KB
#define SM_A1  16384
#define SM_B0  32768                   // 256 rows * 128B = 32KB
#define SM_B1  65536
#define SM_OFF 98304                   // 1152 int offsets
#define SM_TOT 103040
#define EPI_LD 132                     // epilogue [128 oc][132 m] floats

// ---- tf32-preconverted scratch (device globals: allowed scratch) ----
__device__ float g_in_tf[32u * 128u * 64u * 64u];   // 67.1 MB
__device__ float g_wt_tf[256u * KTOT];              // 1.18 MB

__device__ __forceinline__ uint32_t s2u(const void* p) {
    uint32_t a;
    asm("{ .reg .u64 t; cvta.to.shared.u64 t, %1; cvt.u32.u64 %0, t; }" : "=r"(a) : "l"(p));
    return a;
}

__device__ __forceinline__ void ldsm4(uint32_t* r, uint32_t addr) {
    asm volatile("ldmatrix.sync.aligned.m8n8.x4.shared.b16 {%0,%1,%2,%3}, [%4];"
        : "=r"(r[0]), "=r"(r[1]), "=r"(r[2]), "=r"(r[3]) : "r"(addr));
}

__device__ __forceinline__ float f2tf(float f) {
    uint32_t o;
    asm("cvt.rna.tf32.f32 %0, %1;" : "=r"(o) : "f"(f));
    return __uint_as_float(o);
}

__device__ __forceinline__ void mma8(float* d, const uint32_t* a, const uint32_t* b) {
    asm volatile("mma.sync.aligned.m16n8k8.row.col.f32.tf32.tf32.f32 "
        "{%0,%1,%2,%3}, {%4,%5,%6,%7}, {%8,%9}, {%0,%1,%2,%3};"
        : "+f"(d[0]), "+f"(d[1]), "+f"(d[2]), "+f"(d[3])
        : "r"(a[0]), "r"(a[1]), "r"(a[2]), "r"(a[3]), "r"(b[0]), "r"(b[1]));
}

#define CP16(dst, src) \
    asm volatile("cp.async.cg.shared.global [%0], [%1], 16;" :: "r"(dst), "l"(src) : "memory")
#define CP_COMMIT()  asm volatile("cp.async.commit_group;" ::: "memory")
#define CP_WAIT0()   asm volatile("cp.async.wait_group 0;" ::: "memory")
#define STS128(a, r) \
    asm volatile("st.shared.v4.b32 [%0], {%1,%2,%3,%4};" :: "r"(a), \
        "r"(__float_as_uint((r)[0])), "r"(__float_as_uint((r)[1])), \
        "r"(__float_as_uint((r)[2])), "r"(__float_as_uint((r)[3])) : "memory")

// ---- prepass: f32 -> tf32 bit patterns, vectorized ----
__global__ __launch_bounds__(256) void cvt_in_kernel(const float4* __restrict__ src) {
    float4* dst = reinterpret_cast<float4*>(g_in_tf);
    const int n4 = (32 * 128 * 64 * 64) / 4;
    for (int i = blockIdx.x * blockDim.x + threadIdx.x; i < n4; i += gridDim.x * blockDim.x) {
        float4 v = src[i];
        v.x = f2tf(v.x); v.y = f2tf(v.y); v.z = f2tf(v.z); v.w = f2tf(v.w);
        dst[i] = v;
    }
}
__global__ __launch_bounds__(256) void cvt_wt_kernel(const float4* __restrict__ src) {
    float4* dst = reinterpret_cast<float4*>(g_wt_tf);
    const int n4 = (256 * KTOT) / 4;
    for (int i = blockIdx.x * blockDim.x + threadIdx.x; i < n4; i += gridDim.x * blockDim.x) {
        float4 v = src[i];
        v.x = f2tf(v.x); v.y = f2tf(v.y); v.z = f2tf(v.z); v.w = f2tf(v.w);
        dst[i] = v;
    }
}

__global__ __launch_bounds__(NTHR, 1)
void conv2d_tf32_mmasync(float* __restrict__ out)
{
    extern __shared__ char smem[];
    const uint32_t sb = s2u(smem);
    float* smf = (float*)smem;
    int* offs = (int*)(smem + SM_OFF);

    const int tid = threadIdx.x;
    const int wid = tid >> 5, lane = tid & 31;
    const int n   = blockIdx.y;
    const int oh0 = blockIdx.x * 2;

    // k -> input offset table (floats): ic*4096 + kh*64 + kw
    for (int k = tid; k < KTOT; k += NTHR) {
        int ic = k / 9, t9 = k - ic * 9;
        int kh = t9 / 3, kw = t9 - kh * 3;
        offs[k] = ic * 4096 + kh * 64 + kw;
    }

    // ---- A staging: thread = (m = tid&127, k-half aq = tid>>7) ----
    const float* in_n = g_in_tf + (size_t)n * 128 * 64 * 64;
    const float* wtp  = g_wt_tf;
    const int am = tid & 127, aq = tid >> 7;          // aq in 0..1 (16 k each)
    const int aow = am & 63;
    const float* abase = in_n + (size_t)(oh0 + (am >> 6)) * 64 + (aow < 62 ? aow : 0);
    const uint32_t axm_st = (uint32_t)(am & 7) << 4;
    uint32_t asts[4];
    #pragma unroll
    for (int q = 0; q < 4; q++)
        asts[q] = (uint32_t)am * 128 + (((uint32_t)(aq * 64 + q * 16)) ^ axm_st);

    // ---- B staging: thread = (oc-block bocb = tid>>3, quad bq = tid&7) ----
    const int bq = tid & 7, bocb = tid >> 3;          // bocb in 0..31
    const uint32_t bstcol = ((uint32_t)bq * 16) ^ ((uint32_t)(bocb & 7) << 4);

    // ---- warp tiling: 2x4 grid, warp tile m64 x n64 ----
    const int m0 = (wid & 1) * 64, n0 = (wid >> 1) * 64;
    const int T = lane >> 3, rowin = lane & 7;
    const uint32_t acol = (uint32_t)(T >> 1) << 4;
    const uint32_t bcol = (uint32_t)(T & 1) << 4;
    uint32_t arow[4], axm[4], brow[4], bxm[4];
    #pragma unroll
    for (int mi = 0; mi < 4; mi++) {
        int r = m0 + mi * 16 + ((T & 1) << 3) + rowin;
        arow[mi] = (uint32_t)r * 128; axm[mi] = (uint32_t)(r & 7) << 4;
    }
    #pragma unroll
    for (int nb = 0; nb < 4; nb++) {
        int r = n0 + nb * 16 + ((T >> 1) << 3) + rowin;
        brow[nb] = (uint32_t)r * 128; bxm[nb] = (uint32_t)(r & 7) << 4;
    }

    float acc[4][8][4];
    #pragma unroll
    for (int i = 0; i < 4; i++)
        #pragma unroll
        for (int j = 0; j < 8; j++)
            #pragma unroll
            for (int v = 0; v < 4; v++) acc[i][j][v] = 0.0f;

    __syncthreads();   // offs table ready

    float ar[16];
    // ---- prologue: chunk 0 ----
    {
        const int kb = aq * 16;
        #pragma unroll
        for (int j = 0; j < 16; j++) ar[j] = abase[offs[kb + j]];
        const uint32_t Bs = sb + SM_B0;
        #pragma unroll
        for (int j = 0; j < 8; j++) {
            int oc = j * 32 + bocb;
            CP16(Bs + (uint32_t)oc * 128 + bstcol, wtp + (size_t)oc * KTOT + bq * 4);
        }
        CP_COMMIT();
        const uint32_t As = sb + SM_A0;
        #pragma unroll
        for (int q = 0; q < 4; q++) STS128(As + asts[q], ar + 4 * q);
        CP_WAIT0();
    }
    __syncthreads();

    #pragma unroll 1
    for (int kc = 0; kc < NCH; kc++) {
        const uint32_t As = sb + ((kc & 1) ? SM_A1 : SM_A0);
        const uint32_t Bs = sb + ((kc & 1) ? SM_B1 : SM_B0);
        const uint32_t An = sb + ((kc & 1) ? SM_A0 : SM_A1);
        const uint32_t Bn = sb + ((kc & 1) ? SM_B0 : SM_B1);

        if (kc + 1 < NCH) {   // issue next-chunk loads before compute
            const int kb = (kc + 1) * 32 + aq * 16;
            #pragma unroll
            for (int j = 0; j < 16; j++) ar[j] = abase[offs[kb + j]];
            #pragma unroll
            for (int j = 0; j < 8; j++) {
                int oc = j * 32 + bocb;
                CP16(Bn + (uint32_t)oc * 128 + bstcol,
                     wtp + (size_t)oc * KTOT + (kc + 1) * 32 + bq * 4);
            }
            CP_COMMIT();
        }

        // ---- compute chunk kc: pure ldmatrix + mma, m64n64 per warp ----
        #pragma unroll
        for (int s = 0; s < 4; s++) {
            uint32_t a[4][4], b[4][4];
            #pragma unroll
            for (int mi = 0; mi < 4; mi++)
                ldsm4(a[mi], As + arow[mi] + ((acol | ((uint32_t)s << 5)) ^ axm[mi]));
            #pragma unroll
            for (int nb = 0; nb < 4; nb++)
                ldsm4(b[nb], Bs + brow[nb] + ((bcol | ((uint32_t)s << 5)) ^ bxm[nb]));
            #pragma unroll
            for (int mi = 0; mi < 4; mi++)
                #pragma unroll
                for (int nb = 0; nb < 4; nb++) {
                    mma8(acc[mi][2 * nb],     a[mi], &b[nb][0]);
                    mma8(acc[mi][2 * nb + 1], a[mi], &b[nb][2]);
                }
        }

        if (kc + 1 < NCH) {   // finish next-chunk staging
            #pragma unroll
            for (int q = 0; q < 4; q++) STS128(An + asts[q], ar + 4 * q);
            CP_WAIT0();
        }
        __syncthreads();      // single barrier per chunk
    }

    // ---- epilogue: smem transpose to [oc][m], coalesced stores ----
    const int eg = lane >> 2, ee = lane & 3;
    #pragma unroll 1
    for (int p = 0; p < 2; p++) {
        if ((n0 >> 7) == p) {
            #pragma unroll
            for (int mi = 0; mi < 4; mi++)
                #pragma unroll
                for (int nj = 0; nj < 8; nj++) {
                    int ocl = (n0 & 127) + nj * 8 + 2 * ee;
                    int mm  = m0 + mi * 16 + eg;
                    smf[ocl * EPI_LD + mm]           = acc[mi][nj][0];
                    smf[(ocl + 1) * EPI_LD + mm]     = acc[mi][nj][1];
                    smf[ocl * EPI_LD + mm + 8]       = acc[mi][nj][2];
                    smf[(ocl + 1) * EPI_LD + mm + 8] = acc[mi][nj][3];
                }
        }
        __syncthreads();
        #pragma unroll 4
        for (int i = 0; i < 64; i++) {
            int idx = i * NTHR + tid;
            int mm = idx & 127, ocl = idx >> 7;
            int ow = mm & 63, oh = oh0 + (mm >> 6);
            if (ow < 62)
                out[((size_t)n * 256 + p * 128 + ocl) * 3844 + (size_t)oh * 62 + ow]
                    = smf[ocl * EPI_LD + mm];
        }
        __syncthreads();
    }
}

extern "C" void kernel_launch(void* const* d_in, const int* in_sizes, int n_in,
                              void* d_out, int out_size)
{
    const float* in = (const float*)d_in[0];   // [32,128,64,64]
    const float* wt = (const float*)d_in[1];   // [256,128,3,3]
    float* out = (float*)d_out;                // [32,256,62,62]

    // prepass: convert input + weights to tf32 bit patterns
    cvt_in_kernel<<<2048, 256>>>(reinterpret_cast<const float4*>(in));
    cvt_wt_kernel<<<288, 256>>>(reinterpret_cast<const float4*>(wt));

    cudaFuncSetAttribute(conv2d_tf32_mmasync,
                         cudaFuncAttributeMaxDynamicSharedMemorySize, SM_TOT);
    dim3 grid(31, 32);
    conv2d_tf32_mmasync<<<grid, NTHR, SM_TOT>>>(out);
}

// round 8
// speedup vs baseline: 1.4844x; 1.0088x over previous
#include <cuda_runtime.h>
#include <cstdint>

#define NTHR 512
#define KTOT 1152
#define NBLK 36          // K blocks of 32

// smem layout (bytes) — 4-deep buffers, swizzled 128B rows
#define SM_A   0                       // 4 x (128 rows * 128B) = 64KB
#define SM_B   65536                   // 4 x (256 rows * 128B) = 128KB
#define SM_OFF 196608                  // 1152 int offsets
#define SM_TOT 201216
#define EPI_LD 132                     // epilogue [128 oc][132 m] floats

// ---- tf32-preconverted scratch (device globals: allowed scratch) ----
__device__ float g_in_tf[32u * 128u * 64u * 64u];   // 67.1 MB
__device__ float g_wt_tf[256u * KTOT];              // 1.18 MB

__device__ __forceinline__ uint32_t s2u(const void* p) {
    uint32_t a;
    asm("{ .reg .u64 t; cvta.to.shared.u64 t, %1; cvt.u32.u64 %0, t; }" : "=r"(a) : "l"(p));
    return a;
}

__device__ __forceinline__ void ldsm4(uint32_t* r, uint32_t addr) {
    asm volatile("ldmatrix.sync.aligned.m8n8.x4.shared.b16 {%0,%1,%2,%3}, [%4];"
        : "=r"(r[0]), "=r"(r[1]), "=r"(r[2]), "=r"(r[3]) : "r"(addr));
}

__device__ __forceinline__ float f2tf(float f) {
    uint32_t o;
    asm("cvt.rna.tf32.f32 %0, %1;" : "=r"(o) : "f"(f));
    return __uint_as_float(o);
}

__device__ __forceinline__ void mma8(float* d, const uint32_t* a, const uint32_t* b) {
    asm volatile("mma.sync.aligned.m16n8k8.row.col.f32.tf32.tf32.f32 "
        "{%0,%1,%2,%3}, {%4,%5,%6,%7}, {%8,%9}, {%0,%1,%2,%3};"
        : "+f"(d[0]), "+f"(d[1]), "+f"(d[2]), "+f"(d[3])
        : "r"(a[0]), "r"(a[1]), "r"(a[2]), "r"(a[3]), "r"(b[0]), "r"(b[1]));
}

#define CP16(dst, src) \
    asm volatile("cp.async.cg.shared.global [%0], [%1], 16;" :: "r"(dst), "l"(src) : "memory")
#define CP_COMMIT()  asm volatile("cp.async.commit_group;" ::: "memory")
#define CP_WAIT0()   asm volatile("cp.async.wait_group 0;" ::: "memory")
#define STS128(a, r) \
    asm volatile("st.shared.v4.b32 [%0], {%1,%2,%3,%4};" :: "r"(a), \
        "r"(__float_as_uint((r)[0])), "r"(__float_as_uint((r)[1])), \
        "r"(__float_as_uint((r)[2])), "r"(__float_as_uint((r)[3])) : "memory")

// ---- prepass: f32 -> tf32 bit patterns, vectorized ----
__global__ __launch_bounds__(256) void cvt_in_kernel(const float4* __restrict__ src) {
    float4* dst = reinterpret_cast<float4*>(g_in_tf);
    const int n4 = (32 * 128 * 64 * 64) / 4;
    for (int i = blockIdx.x * blockDim.x + threadIdx.x; i < n4; i += gridDim.x * blockDim.x) {
        float4 v = src[i];
        v.x = f2tf(v.x); v.y = f2tf(v.y); v.z = f2tf(v.z); v.w = f2tf(v.w);
        dst[i] = v;
    }
}
__global__ __launch_bounds__(256) void cvt_wt_kernel(const float4* __restrict__ src) {
    float4* dst = reinterpret_cast<float4*>(g_wt_tf);
    const int n4 = (256 * KTOT) / 4;
    for (int i = blockIdx.x * blockDim.x + threadIdx.x; i < n4; i += gridDim.x * blockDim.x) {
        float4 v = src[i];
        v.x = f2tf(v.x); v.y = f2tf(v.y); v.z = f2tf(v.z); v.w = f2tf(v.w);
        dst[i] = v;
    }
}

__global__ __launch_bounds__(NTHR, 1)
void conv2d_tf32_mmasync(float* __restrict__ out)
{
    extern __shared__ char smem[];
    const uint32_t sb = s2u(smem);
    float* smf = (float*)smem;
    int* offs = (int*)(smem + SM_OFF);

    const int tid = threadIdx.x;
    const int wid = tid >> 5, lane = tid & 31;
    const int n   = blockIdx.y;
    const int oh0 = blockIdx.x * 2;

    // k -> input offset table (floats): ic*4096 + kh*64 + kw
    for (int k = tid; k < KTOT; k += NTHR) {
        int ic = k / 9, t9 = k - ic * 9;
        int kh = t9 / 3, kw = t9 - kh * 3;
        offs[k] = ic * 4096 + kh * 64 + kw;
    }

    // ---- A staging: thread = (m = tid&127, k-octet aq = tid>>7) ----
    const float* in_n = g_in_tf + (size_t)n * 128 * 64 * 64;
    const float* wtp  = g_wt_tf;
    const int am = tid & 127, aq = tid >> 7;          // aq in 0..3
    const int aow = am & 63;
    const float* abase = in_n + (size_t)(oh0 + (am >> 6)) * 64 + (aow < 62 ? aow : 0);
    const uint32_t axm_st  = (uint32_t)(am & 7) << 4;
    const uint32_t asts0 = (uint32_t)am * 128 + (((uint32_t)aq * 32)      ^ axm_st);
    const uint32_t asts1 = (uint32_t)am * 128 + (((uint32_t)aq * 32 + 16) ^ axm_st);

    // ---- B staging: thread = (oc-block bocb = tid>>3, quad bq = tid&7) ----
    const int bq = tid & 7, bocb = tid >> 3;          // bocb in 0..63
    const uint32_t bstcol = ((uint32_t)bq * 16) ^ ((uint32_t)(bocb & 7) << 4);

    // ---- warp tiling: 4x4 grid, warp tile m32 x n64 ----
    const int m0 = (wid & 3) * 32, n0 = (wid >> 2) * 64;
    const int T = lane >> 3, rowin = lane & 7;
    const uint32_t acol = (uint32_t)(T >> 1) << 4;
    const uint32_t bcol = (uint32_t)(T & 1) << 4;
    uint32_t arow[2], axm[2], brow[4], bxm[4];
    #pragma unroll
    for (int mi = 0; mi < 2; mi++) {
        int r = m0 + mi * 16 + ((T & 1) << 3) + rowin;
        arow[mi] = (uint32_t)r * 128; axm[mi] = (uint32_t)(r & 7) << 4;
    }
    #pragma unroll
    for (int nb = 0; nb < 4; nb++) {
        int r = n0 + nb * 16 + ((T >> 1) << 3) + rowin;
        brow[nb] = (uint32_t)r * 128; bxm[nb] = (uint32_t)(r & 7) << 4;
    }

    float acc[2][8][4];
    #pragma unroll
    for (int i = 0; i < 2; i++)
        #pragma unroll
        for (int j = 0; j < 8; j++)
            #pragma unroll
            for (int v = 0; v < 4; v++) acc[i][j][v] = 0.0f;

    __syncthreads();   // offs table ready

    float ar[8];
    // ---- prologue: stage blocks 0 and 1 into buffers 0,1 ----
    #pragma unroll
    for (int blk = 0; blk < 2; blk++) {
        const int kb = blk * 32 + aq * 8;
        #pragma unroll
        for (int j = 0; j < 8; j++) ar[j] = abase[offs[kb + j]];
        const uint32_t Bs = sb + SM_B + (uint32_t)blk * 32768;
        #pragma unroll
        for (int j = 0; j < 4; j++) {
            int oc = j * 64 + bocb;
            CP16(Bs + (uint32_t)oc * 128 + bstcol,
                 wtp + (size_t)oc * KTOT + blk * 32 + bq * 4);
        }
        const uint32_t As = sb + SM_A + (uint32_t)blk * 16384;
        STS128(As + asts0, ar);
        STS128(As + asts1, ar + 4);
    }
    CP_COMMIT();
    CP_WAIT0();
    __syncthreads();

    #pragma unroll 1
    for (int j2 = 0; j2 < NBLK; j2 += 2) {
        const bool more = (j2 + 2 < NBLK);

        // issue B cp.async for blocks j2+2, j2+3 and A LDG for block j2+2
        if (more) {
            #pragma unroll
            for (int blk = 0; blk < 2; blk++) {
                const int jb = j2 + 2 + blk;
                const uint32_t Bs = sb + SM_B + (uint32_t)(jb & 3) * 32768;
                #pragma unroll
                for (int j = 0; j < 4; j++) {
                    int oc = j * 64 + bocb;
                    CP16(Bs + (uint32_t)oc * 128 + bstcol,
                         wtp + (size_t)oc * KTOT + jb * 32 + bq * 4);
                }
            }
            CP_COMMIT();
            const int kb = (j2 + 2) * 32 + aq * 8;
            #pragma unroll
            for (int j = 0; j < 8; j++) ar[j] = abase[offs[kb + j]];
        }

        // ---- compute block j2 ----
        {
            const uint32_t As = sb + SM_A + (uint32_t)(j2 & 3) * 16384;
            const uint32_t Bs = sb + SM_B + (uint32_t)(j2 & 3) * 32768;
            #pragma unroll
            for (int s = 0; s < 4; s++) {
                uint32_t a[2][4], b[4][4];
                #pragma unroll
                for (int mi = 0; mi < 2; mi++)
                    ldsm4(a[mi], As + arow[mi] + ((acol | ((uint32_t)s << 5)) ^ axm[mi]));
                #pragma unroll
                for (int nb = 0; nb < 4; nb++)
                    ldsm4(b[nb], Bs + brow[nb] + ((bcol | ((uint32_t)s << 5)) ^ bxm[nb]));
                #pragma unroll
                for (int mi = 0; mi < 2; mi++)
                    #pragma unroll
                    for (int nb = 0; nb < 4; nb++) {
                        mma8(acc[mi][2 * nb],     a[mi], &b[nb][0]);
                        mma8(acc[mi][2 * nb + 1], a[mi], &b[nb][2]);
                    }
            }
        }

        // store A block j2+2, load A block j2+3
        if (more) {
            const uint32_t An = sb + SM_A + (uint32_t)((j2 + 2) & 3) * 16384;
            STS128(An + asts0, ar);
            STS128(An + asts1, ar + 4);
            const int kb = (j2 + 3) * 32 + aq * 8;
            #pragma unroll
            for (int j = 0; j < 8; j++) ar[j] = abase[offs[kb + j]];
        }

        // ---- compute block j2+1 ----
        {
            const uint32_t As = sb + SM_A + (uint32_t)((j2 + 1) & 3) * 16384;
            const uint32_t Bs = sb + SM_B + (uint32_t)((j2 + 1) & 3) * 32768;
            #pragma unroll
            for (int s = 0; s < 4; s++) {
                uint32_t a[2][4], b[4][4];
                #pragma unroll
                for (int mi = 0; mi < 2; mi++)
                    ldsm4(a[mi], As + arow[mi] + ((acol | ((uint32_t)s << 5)) ^ axm[mi]));
                #pragma unroll
                for (int nb = 0; nb < 4; nb++)
                    ldsm4(b[nb], Bs + brow[nb] + ((bcol | ((uint32_t)s << 5)) ^ bxm[nb]));
                #pragma unroll
                for (int mi = 0; mi < 2; mi++)
                    #pragma unroll
                    for (int nb = 0; nb < 4; nb++) {
                        mma8(acc[mi][2 * nb],     a[mi], &b[nb][0]);
                        mma8(acc[mi][2 * nb + 1], a[mi], &b[nb][2]);
                    }
            }
        }

        if (more) {
            const uint32_t An = sb + SM_A + (uint32_t)((j2 + 3) & 3) * 16384;
            STS128(An + asts0, ar);
            STS128(An + asts1, ar + 4);
            CP_WAIT0();
        }
        __syncthreads();      // single barrier per 2-block stage
    }

    // ---- epilogue: smem transpose to [oc][m], coalesced stores ----
    const int eg = lane >> 2, ee = lane & 3;
    #pragma unroll 1
    for (int p = 0; p < 2; p++) {
        if ((n0 >> 7) == p) {
            #pragma unroll
            for (int mi = 0; mi < 2; mi++)
                #pragma unroll
                for (int nj = 0; nj < 8; nj++) {
                    int ocl = (n0 & 127) + nj * 8 + 2 * ee;
                    int mm  = m0 + mi * 16 + eg;
                    smf[ocl * EPI_LD + mm]           = acc[mi][nj][0];
                    smf[(ocl + 1) * EPI_LD + mm]     = acc[mi][nj][1];
                    smf[ocl * EPI_LD + mm + 8]       = acc[mi][nj][2];
                    smf[(ocl + 1) * EPI_LD + mm + 8] = acc[mi][nj][3];
                }
        }
        __syncthreads();
        #pragma unroll 4
        for (int i = 0; i < 32; i++) {
            int idx = i * NTHR + tid;
            int mm = idx & 127, ocl = idx >> 7;
            int ow = mm & 63, oh = oh0 + (mm >> 6);
            if (ow < 62)
                out[((size_t)n * 256 + p * 128 + ocl) * 3844 + (size_t)oh * 62 + ow]
                    = smf[ocl * EPI_LD + mm];
        }
        __syncthreads();
    }
}

extern "C" void kernel_launch(void* const* d_in, const int* in_sizes, int n_in,
                              void* d_out, int out_size)
{
    const float* in = (const float*)d_in[0];   // [32,128,64,64]
    const float* wt = (const float*)d_in[1];   // [256,128,3,3]
    float* out = (float*)d_out;                // [32,256,62,62]

    // prepass: convert input + weights to tf32 bit patterns
    cvt_in_kernel<<<2048, 256>>>(reinterpret_cast<const float4*>(in));
    cvt_wt_kernel<<<288, 256>>>(reinterpret_cast<const float4*>(wt));

    cudaFuncSetAttribute(conv2d_tf32_mmasync,
                         cudaFuncAttributeMaxDynamicSharedMemorySize, SM_TOT);
    dim3 grid(31, 32);
    conv2d_tf32_mmasync<<<grid, NTHR, SM_TOT>>>(out);
}

// round 9
// speedup vs baseline: 1.4863x; 1.0013x over previous
#include <cuda_runtime.h>
#include <cstdint>

#define NTHR 512
#define KTOT 1152
#define NBLK 36          // K blocks of 32

// smem layout (bytes) — 4-deep buffers, swizzled 128B rows
#define SM_A   0                       // 4 x (128 rows * 128B) = 64KB
#define SM_B   65536                   // 4 x (256 rows * 128B) = 128KB
#define SM_OFF 196608                  // 1152 int offsets
#define SM_TOT 201216
#define EPI_LD 132                     // epilogue [128 oc][132 m] floats

// ---- tf32-preconverted scratch (device globals: allowed scratch) ----
__device__ float g_in_tf[32u * 128u * 64u * 64u];   // 67.1 MB
__device__ float g_wt_tf[256u * KTOT];              // 1.18 MB

__device__ __forceinline__ uint32_t s2u(const void* p) {
    uint32_t a;
    asm("{ .reg .u64 t; cvta.to.shared.u64 t, %1; cvt.u32.u64 %0, t; }" : "=r"(a) : "l"(p));
    return a;
}

__device__ __forceinline__ void ldsm4(uint32_t* r, uint32_t addr) {
    asm volatile("ldmatrix.sync.aligned.m8n8.x4.shared.b16 {%0,%1,%2,%3}, [%4];"
        : "=r"(r[0]), "=r"(r[1]), "=r"(r[2]), "=r"(r[3]) : "r"(addr));
}

__device__ __forceinline__ float f2tf(float f) {
    uint32_t o;
    asm("cvt.rna.tf32.f32 %0, %1;" : "=r"(o) : "f"(f));
    return __uint_as_float(o);
}

__device__ __forceinline__ void mma8(float* d, const uint32_t* a, const uint32_t* b) {
    asm volatile("mma.sync.aligned.m16n8k8.row.col.f32.tf32.tf32.f32 "
        "{%0,%1,%2,%3}, {%4,%5,%6,%7}, {%8,%9}, {%0,%1,%2,%3};"
        : "+f"(d[0]), "+f"(d[1]), "+f"(d[2]), "+f"(d[3])
        : "r"(a[0]), "r"(a[1]), "r"(a[2]), "r"(a[3]), "r"(b[0]), "r"(b[1]));
}

#define CP16(dst, src) \
    asm volatile("cp.async.cg.shared.global [%0], [%1], 16;" :: "r"(dst), "l"(src) : "memory")
#define CP_COMMIT()  asm volatile("cp.async.commit_group;" ::: "memory")
#define CP_WAIT0()   asm volatile("cp.async.wait_group 0;" ::: "memory")
#define STS128(a, r) \
    asm volatile("st.shared.v4.b32 [%0], {%1,%2,%3,%4};" :: "r"(a), \
        "r"(__float_as_uint((r)[0])), "r"(__float_as_uint((r)[1])), \
        "r"(__float_as_uint((r)[2])), "r"(__float_as_uint((r)[3])) : "memory")

// ---- prepass: f32 -> tf32 bit patterns, vectorized ----
__global__ __launch_bounds__(256) void cvt_in_kernel(const float4* __restrict__ src) {
    float4* dst = reinterpret_cast<float4*>(g_in_tf);
    const int n4 = (32 * 128 * 64 * 64) / 4;
    for (int i = blockIdx.x * blockDim.x + threadIdx.x; i < n4; i += gridDim.x * blockDim.x) {
        float4 v = src[i];
        v.x = f2tf(v.x); v.y = f2tf(v.y); v.z = f2tf(v.z); v.w = f2tf(v.w);
        dst[i] = v;
    }
}
__global__ __launch_bounds__(256) void cvt_wt_kernel(const float4* __restrict__ src) {
    float4* dst = reinterpret_cast<float4*>(g_wt_tf);
    const int n4 = (256 * KTOT) / 4;
    for (int i = blockIdx.x * blockDim.x + threadIdx.x; i < n4; i += gridDim.x * blockDim.x) {
        float4 v = src[i];
        v.x = f2tf(v.x); v.y = f2tf(v.y); v.z = f2tf(v.z); v.w = f2tf(v.w);
        dst[i] = v;
    }
}

__global__ __launch_bounds__(NTHR, 1)
void conv2d_tf32_mmasync(float* __restrict__ out)
{
    extern __shared__ char smem[];
    const uint32_t sb = s2u(smem);
    float* smf = (float*)smem;
    int* offs = (int*)(smem + SM_OFF);

    const int tid = threadIdx.x;
    const int wid = tid >> 5, lane = tid & 31;
    const int n   = blockIdx.y;
    const int oh0 = blockIdx.x * 2;

    // k -> input offset table (floats): ic*4096 + kh*64 + kw
    for (int k = tid; k < KTOT; k += NTHR) {
        int ic = k / 9, t9 = k - ic * 9;
        int kh = t9 / 3, kw = t9 - kh * 3;
        offs[k] = ic * 4096 + kh * 64 + kw;
    }

    // ---- A staging: thread = (m = tid&127, k-octet aq = tid>>7) ----
    const float* in_n = g_in_tf + (size_t)n * 128 * 64 * 64;
    const float* wtp  = g_wt_tf;
    const int am = tid & 127, aq = tid >> 7;          // aq in 0..3
    const int aow = am & 63;
    const float* abase = in_n + (size_t)(oh0 + (am >> 6)) * 64 + (aow < 62 ? aow : 0);
    const uint32_t axm_st  = (uint32_t)(am & 7) << 4;
    const uint32_t asts0 = (uint32_t)am * 128 + (((uint32_t)aq * 32)      ^ axm_st);
    const uint32_t asts1 = (uint32_t)am * 128 + (((uint32_t)aq * 32 + 16) ^ axm_st);

    // ---- B staging: thread = (oc-block bocb = tid>>3, quad bq = tid&7) ----
    const int bq = tid & 7, bocb = tid >> 3;          // bocb in 0..63
    const uint32_t bstcol = ((uint32_t)bq * 16) ^ ((uint32_t)(bocb & 7) << 4);

    // ---- warp tiling: 4x4 grid, warp tile m32 x n64 ----
    const int m0 = (wid & 3) * 32, n0 = (wid >> 2) * 64;
    const int T = lane >> 3, rowin = lane & 7;
    const uint32_t acol = (uint32_t)(T >> 1) << 4;
    const uint32_t bcol = (uint32_t)(T & 1) << 4;
    uint32_t arow[2], axm[2], brow[4], bxm[4];
    #pragma unroll
    for (int mi = 0; mi < 2; mi++) {
        int r = m0 + mi * 16 + ((T & 1) << 3) + rowin;
        arow[mi] = (uint32_t)r * 128; axm[mi] = (uint32_t)(r & 7) << 4;
    }
    #pragma unroll
    for (int nb = 0; nb < 4; nb++) {
        int r = n0 + nb * 16 + ((T >> 1) << 3) + rowin;
        brow[nb] = (uint32_t)r * 128; bxm[nb] = (uint32_t)(r & 7) << 4;
    }

    float acc[2][8][4];
    #pragma unroll
    for (int i = 0; i < 2; i++)
        #pragma unroll
        for (int j = 0; j < 8; j++)
            #pragma unroll
            for (int v = 0; v < 4; v++) acc[i][j][v] = 0.0f;

    __syncthreads();   // offs table ready

    float ar[8];
    // ---- prologue: stage blocks 0 and 1 into buffers 0,1 ----
    #pragma unroll
    for (int blk = 0; blk < 2; blk++) {
        const int kb = blk * 32 + aq * 8;
        #pragma unroll
        for (int j = 0; j < 8; j++) ar[j] = abase[offs[kb + j]];
        const uint32_t Bs = sb + SM_B + (uint32_t)blk * 32768;
        #pragma unroll
        for (int j = 0; j < 4; j++) {
            int oc = j * 64 + bocb;
            CP16(Bs + (uint32_t)oc * 128 + bstcol,
                 wtp + (size_t)oc * KTOT + blk * 32 + bq * 4);
        }
        const uint32_t As = sb + SM_A + (uint32_t)blk * 16384;
        STS128(As + asts0, ar);
        STS128(As + asts1, ar + 4);
    }
    CP_COMMIT();
    CP_WAIT0();
    __syncthreads();

    #pragma unroll 1
    for (int j2 = 0; j2 < NBLK; j2 += 2) {
        const bool more = (j2 + 2 < NBLK);

        // issue B cp.async for blocks j2+2, j2+3 and A LDG for block j2+2
        if (more) {
            #pragma unroll
            for (int blk = 0; blk < 2; blk++) {
                const int jb = j2 + 2 + blk;
                const uint32_t Bs = sb + SM_B + (uint32_t)(jb & 3) * 32768;
                #pragma unroll
                for (int j = 0; j < 4; j++) {
                    int oc = j * 64 + bocb;
                    CP16(Bs + (uint32_t)oc * 128 + bstcol,
                         wtp + (size_t)oc * KTOT + jb * 32 + bq * 4);
                }
            }
            CP_COMMIT();
            const int kb = (j2 + 2) * 32 + aq * 8;
            #pragma unroll
            for (int j = 0; j < 8; j++) ar[j] = abase[offs[kb + j]];
        }

        // ---- compute block j2 ----
        {
            const uint32_t As = sb + SM_A + (uint32_t)(j2 & 3) * 16384;
            const uint32_t Bs = sb + SM_B + (uint32_t)(j2 & 3) * 32768;
            #pragma unroll
            for (int s = 0; s < 4; s++) {
                uint32_t a[2][4], b[4][4];
                #pragma unroll
                for (int mi = 0; mi < 2; mi++)
                    ldsm4(a[mi], As + arow[mi] + ((acol | ((uint32_t)s << 5)) ^ axm[mi]));
                #pragma unroll
                for (int nb = 0; nb < 4; nb++)
                    ldsm4(b[nb], Bs + brow[nb] + ((bcol | ((uint32_t)s << 5)) ^ bxm[nb]));
                #pragma unroll
                for (int mi = 0; mi < 2; mi++)
                    #pragma unroll
                    for (int nb = 0; nb < 4; nb++) {
                        mma8(acc[mi][2 * nb],     a[mi], &b[nb][0]);
                        mma8(acc[mi][2 * nb + 1], a[mi], &b[nb][2]);
                    }
            }
        }

        // store A block j2+2, load A block j2+3
        if (more) {
            const uint32_t An = sb + SM_A + (uint32_t)((j2 + 2) & 3) * 16384;
            STS128(An + asts0, ar);
            STS128(An + asts1, ar + 4);
            const int kb = (j2 + 3) * 32 + aq * 8;
            #pragma unroll
            for (int j = 0; j < 8; j++) ar[j] = abase[offs[kb + j]];
        }

        // ---- compute block j2+1 ----
        {
            const uint32_t As = sb + SM_A + (uint32_t)((j2 + 1) & 3) * 16384;
            const uint32_t Bs = sb + SM_B + (uint32_t)((j2 + 1) & 3) * 32768;
            #pragma unroll
            for (int s = 0; s < 4; s++) {
                uint32_t a[2][4], b[4][4];
                #pragma unroll
                for (int mi = 0; mi < 2; mi++)
                    ldsm4(a[mi], As + arow[mi] + ((acol | ((uint32_t)s << 5)) ^ axm[mi]));
                #pragma unroll
                for (int nb = 0; nb < 4; nb++)
                    ldsm4(b[nb], Bs + brow[nb] + ((bcol | ((uint32_t)s << 5)) ^ bxm[nb]));
                #pragma unroll
                for (int mi = 0; mi < 2; mi++)
                    #pragma unroll
                    for (int nb = 0; nb < 4; nb++) {
                        mma8(acc[mi][2 * nb],     a[mi], &b[nb][0]);
                        mma8(acc[mi][2 * nb + 1], a[mi], &b[nb][2]);
                    }
            }
        }

        if (more) {
            const uint32_t An = sb + SM_A + (uint32_t)((j2 + 3) & 3) * 16384;
            STS128(An + asts0, ar);
            STS128(An + asts1, ar + 4);
            CP_WAIT0();
        }
        __syncthreads();      // single barrier per 2-block stage
    }

    // ---- epilogue: smem transpose to [oc][m], coalesced stores ----
    const int eg = lane >> 2, ee = lane & 3;
    #pragma unroll 1
    for (int p = 0; p < 2; p++) {
        if ((n0 >> 7) == p) {
            #pragma unroll
            for (int mi = 0; mi < 2; mi++)
                #pragma unroll
                for (int nj = 0; nj < 8; nj++) {
                    int ocl = (n0 & 127) + nj * 8 + 2 * ee;
                    int mm  = m0 + mi * 16 + eg;
                    smf[ocl * EPI_LD + mm]           = acc[mi][nj][0];
                    smf[(ocl + 1) * EPI_LD + mm]     = acc[mi][nj][1];
                    smf[ocl * EPI_LD + mm + 8]       = acc[mi][nj][2];
                    smf[(ocl + 1) * EPI_LD + mm + 8] = acc[mi][nj][3];
                }
        }
        __syncthreads();
        #pragma unroll 4
        for (int i = 0; i < 32; i++) {
            int idx = i * NTHR + tid;
            int mm = idx & 127, ocl = idx >> 7;
            int ow = mm & 63, oh = oh0 + (mm >> 6);
            if (ow < 62)
                out[((size_t)n * 256 + p * 128 + ocl) * 3844 + (size_t)oh * 62 + ow]
                    = smf[ocl * EPI_LD + mm];
        }
        __syncthreads();
    }
}

extern "C" void kernel_launch(void* const* d_in, const int* in_sizes, int n_in,
                              void* d_out, int out_size)
{
    const float* in = (const float*)d_in[0];   // [32,128,64,64]
    const float* wt = (const float*)d_in[1];   // [256,128,3,3]
    float* out = (float*)d_out;                // [32,256,62,62]

    // prepass: convert input + weights to tf32 bit patterns
    cvt_in_kernel<<<2048, 256>>>(reinterpret_cast<const float4*>(in));
    cvt_wt_kernel<<<288, 256>>>(reinterpret_cast<const float4*>(wt));

    cudaFuncSetAttribute(conv2d_tf32_mmasync,
                         cudaFuncAttributeMaxDynamicSharedMemorySize, SM_TOT);
    dim3 grid(31, 32);
    conv2d_tf32_mmasync<<<grid, NTHR, SM_TOT>>>(out);
}

// round 10
// speedup vs baseline: 1.4867x; 1.0003x over previous
#include <cuda_runtime.h>
#include <cstdint>

#define NTHR 512
#define KTOT 1152
#define NBLK 36          // K blocks of 32

// smem layout (bytes) — 4-deep buffers, swizzled 128B rows
#define SM_A   0                       // 4 x (128 rows * 128B) = 64KB
#define SM_B   65536                   // 4 x (256 rows * 128B) = 128KB
#define SM_OFF 196608                  // 1152 int offsets
#define SM_TOT 201216
#define EPI_LD 132                     // epilogue [128 oc][132 m] floats

// ---- tf32-preconverted scratch (device globals: allowed scratch) ----
__device__ float g_in_tf[32u * 128u * 64u * 64u];   // 67.1 MB
__device__ float g_wt_tf[256u * KTOT];              // 1.18 MB

__device__ __forceinline__ uint32_t s2u(const void* p) {
    uint32_t a;
    asm("{ .reg .u64 t; cvta.to.shared.u64 t, %1; cvt.u32.u64 %0, t; }" : "=r"(a) : "l"(p));
    return a;
}

__device__ __forceinline__ void ldsm4(uint32_t* r, uint32_t addr) {
    asm volatile("ldmatrix.sync.aligned.m8n8.x4.shared.b16 {%0,%1,%2,%3}, [%4];"
        : "=r"(r[0]), "=r"(r[1]), "=r"(r[2]), "=r"(r[3]) : "r"(addr));
}

__device__ __forceinline__ float f2tf(float f) {
    uint32_t o;
    asm("cvt.rna.tf32.f32 %0, %1;" : "=r"(o) : "f"(f));
    return __uint_as_float(o);
}

__device__ __forceinline__ void mma8(float* d, const uint32_t* a, const uint32_t* b) {
    asm volatile("mma.sync.aligned.m16n8k8.row.col.f32.tf32.tf32.f32 "
        "{%0,%1,%2,%3}, {%4,%5,%6,%7}, {%8,%9}, {%0,%1,%2,%3};"
        : "+f"(d[0]), "+f"(d[1]), "+f"(d[2]), "+f"(d[3])
        : "r"(a[0]), "r"(a[1]), "r"(a[2]), "r"(a[3]), "r"(b[0]), "r"(b[1]));
}

#define CP16(dst, src) \
    asm volatile("cp.async.cg.shared.global [%0], [%1], 16;" :: "r"(dst), "l"(src) : "memory")
#define CP_COMMIT()  asm volatile("cp.async.commit_group;" ::: "memory")
#define CP_WAIT0()   asm volatile("cp.async.wait_group 0;" ::: "memory")
#define STS128(a, r) \
    asm volatile("st.shared.v4.b32 [%0], {%1,%2,%3,%4};" :: "r"(a), \
        "r"(__float_as_uint((r)[0])), "r"(__float_as_uint((r)[1])), \
        "r"(__float_as_uint((r)[2])), "r"(__float_as_uint((r)[3])) : "memory")

// ---- prepass: f32 -> tf32 bit patterns, vectorized ----
__global__ __launch_bounds__(256) void cvt_in_kernel(const float4* __restrict__ src) {
    float4* dst = reinterpret_cast<float4*>(g_in_tf);
    const int n4 = (32 * 128 * 64 * 64) / 4;
    for (int i = blockIdx.x * blockDim.x + threadIdx.x; i < n4; i += gridDim.x * blockDim.x) {
        float4 v = src[i];
        v.x = f2tf(v.x); v.y = f2tf(v.y); v.z = f2tf(v.z); v.w = f2tf(v.w);
        dst[i] = v;
    }
}
__global__ __launch_bounds__(256) void cvt_wt_kernel(const float4* __restrict__ src) {
    float4* dst = reinterpret_cast<float4*>(g_wt_tf);
    const int n4 = (256 * KTOT) / 4;
    for (int i = blockIdx.x * blockDim.x + threadIdx.x; i < n4; i += gridDim.x * blockDim.x) {
        float4 v = src[i];
        v.x = f2tf(v.x); v.y = f2tf(v.y); v.z = f2tf(v.z); v.w = f2tf(v.w);
        dst[i] = v;
    }
}

__global__ __launch_bounds__(NTHR, 1)
void conv2d_tf32_mmasync(float* __restrict__ out)
{
    extern __shared__ char smem[];
    const uint32_t sb = s2u(smem);
    float* smf = (float*)smem;
    int* offs = (int*)(smem + SM_OFF);

    const int tid = threadIdx.x;
    const int wid = tid >> 5, lane = tid & 31;
    const int n   = blockIdx.y;
    const int oh0 = blockIdx.x * 2;

    // k -> input offset table (floats): ic*4096 + kh*64 + kw
    for (int k = tid; k < KTOT; k += NTHR) {
        int ic = k / 9, t9 = k - ic * 9;
        int kh = t9 / 3, kw = t9 - kh * 3;
        offs[k] = ic * 4096 + kh * 64 + kw;
    }

    // ---- A staging: thread = (m = tid&127, k-octet aq = tid>>7) ----
    const float* in_n = g_in_tf + (size_t)n * 128 * 64 * 64;
    const float* wtp  = g_wt_tf;
    const int am = tid & 127, aq = tid >> 7;          // aq in 0..3
    const int aow = am & 63;
    const float* abase = in_n + (size_t)(oh0 + (am >> 6)) * 64 + (aow < 62 ? aow : 0);
    const uint32_t axm_st  = (uint32_t)(am & 7) << 4;
    const uint32_t asts0 = (uint32_t)am * 128 + (((uint32_t)aq * 32)      ^ axm_st);
    const uint32_t asts1 = (uint32_t)am * 128 + (((uint32_t)aq * 32 + 16) ^ axm_st);

    // ---- B staging: thread = (oc-block bocb = tid>>3, quad bq = tid&7) ----
    const int bq = tid & 7, bocb = tid >> 3;          // bocb in 0..63
    const uint32_t bstcol = ((uint32_t)bq * 16) ^ ((uint32_t)(bocb & 7) << 4);

    // ---- warp tiling: 4x4 grid, warp tile m32 x n64 ----
    const int m0 = (wid & 3) * 32, n0 = (wid >> 2) * 64;
    const int T = lane >> 3, rowin = lane & 7;
    const uint32_t acol = (uint32_t)(T >> 1) << 4;
    const uint32_t bcol = (uint32_t)(T & 1) << 4;
    uint32_t arow[2], axm[2], brow[4], bxm[4];
    #pragma unroll
    for (int mi = 0; mi < 2; mi++) {
        int r = m0 + mi * 16 + ((T & 1) << 3) + rowin;
        arow[mi] = (uint32_t)r * 128; axm[mi] = (uint32_t)(r & 7) << 4;
    }
    #pragma unroll
    for (int nb = 0; nb < 4; nb++) {
        int r = n0 + nb * 16 + ((T >> 1) << 3) + rowin;
        brow[nb] = (uint32_t)r * 128; bxm[nb] = (uint32_t)(r & 7) << 4;
    }

    float acc[2][8][4];
    #pragma unroll
    for (int i = 0; i < 2; i++)
        #pragma unroll
        for (int j = 0; j < 8; j++)
            #pragma unroll
            for (int v = 0; v < 4; v++) acc[i][j][v] = 0.0f;

    __syncthreads();   // offs table ready

    float ar[8];
    // ---- prologue: stage blocks 0 and 1 into buffers 0,1 ----
    #pragma unroll
    for (int blk = 0; blk < 2; blk++) {
        const int kb = blk * 32 + aq * 8;
        #pragma unroll
        for (int j = 0; j < 8; j++) ar[j] = abase[offs[kb + j]];
        const uint32_t Bs = sb + SM_B + (uint32_t)blk * 32768;
        #pragma unroll
        for (int j = 0; j < 4; j++) {
            int oc = j * 64 + bocb;
            CP16(Bs + (uint32_t)oc * 128 + bstcol,
                 wtp + (size_t)oc * KTOT + blk * 32 + bq * 4);
        }
        const uint32_t As = sb + SM_A + (uint32_t)blk * 16384;
        STS128(As + asts0, ar);
        STS128(As + asts1, ar + 4);
    }
    CP_COMMIT();
    CP_WAIT0();
    __syncthreads();

    #pragma unroll 1
    for (int j2 = 0; j2 < NBLK; j2 += 2) {
        const bool more = (j2 + 2 < NBLK);

        // issue B cp.async for blocks j2+2, j2+3 and A LDG for block j2+2
        if (more) {
            #pragma unroll
            for (int blk = 0; blk < 2; blk++) {
                const int jb = j2 + 2 + blk;
                const uint32_t Bs = sb + SM_B + (uint32_t)(jb & 3) * 32768;
                #pragma unroll
                for (int j = 0; j < 4; j++) {
                    int oc = j * 64 + bocb;
                    CP16(Bs + (uint32_t)oc * 128 + bstcol,
                         wtp + (size_t)oc * KTOT + jb * 32 + bq * 4);
                }
            }
            CP_COMMIT();
            const int kb = (j2 + 2) * 32 + aq * 8;
            #pragma unroll
            for (int j = 0; j < 8; j++) ar[j] = abase[offs[kb + j]];
        }

        // ---- compute block j2 ----
        {
            const uint32_t As = sb + SM_A + (uint32_t)(j2 & 3) * 16384;
            const uint32_t Bs = sb + SM_B + (uint32_t)(j2 & 3) * 32768;
            #pragma unroll
            for (int s = 0; s < 4; s++) {
                uint32_t a[2][4], b[4][4];
                #pragma unroll
                for (int mi = 0; mi < 2; mi++)
                    ldsm4(a[mi], As + arow[mi] + ((acol | ((uint32_t)s << 5)) ^ axm[mi]));
                #pragma unroll
                for (int nb = 0; nb < 4; nb++)
                    ldsm4(b[nb], Bs + brow[nb] + ((bcol | ((uint32_t)s << 5)) ^ bxm[nb]));
                #pragma unroll
                for (int mi = 0; mi < 2; mi++)
                    #pragma unroll
                    for (int nb = 0; nb < 4; nb++) {
                        mma8(acc[mi][2 * nb],     a[mi], &b[nb][0]);
                        mma8(acc[mi][2 * nb + 1], a[mi], &b[nb][2]);
                    }
            }
        }

        // store A block j2+2, load A block j2+3
        if (more) {
            const uint32_t An = sb + SM_A + (uint32_t)((j2 + 2) & 3) * 16384;
            STS128(An + asts0, ar);
            STS128(An + asts1, ar + 4);
            const int kb = (j2 + 3) * 32 + aq * 8;
            #pragma unroll
            for (int j = 0; j < 8; j++) ar[j] = abase[offs[kb + j]];
        }

        // ---- compute block j2+1 ----
        {
            const uint32_t As = sb + SM_A + (uint32_t)((j2 + 1) & 3) * 16384;
            const uint32_t Bs = sb + SM_B + (uint32_t)((j2 + 1) & 3) * 32768;
            #pragma unroll
            for (int s = 0; s < 4; s++) {
                uint32_t a[2][4], b[4][4];
                #pragma unroll
                for (int mi = 0; mi < 2; mi++)
                    ldsm4(a[mi], As + arow[mi] + ((acol | ((uint32_t)s << 5)) ^ axm[mi]));
                #pragma unroll
                for (int nb = 0; nb < 4; nb++)
                    ldsm4(b[nb], Bs + brow[nb] + ((bcol | ((uint32_t)s << 5)) ^ bxm[nb]));
                #pragma unroll
                for (int mi = 0; mi < 2; mi++)
                    #pragma unroll
                    for (int nb = 0; nb < 4; nb++) {
                        mma8(acc[mi][2 * nb],     a[mi], &b[nb][0]);
                        mma8(acc[mi][2 * nb + 1], a[mi], &b[nb][2]);
                    }
            }
        }

        if (more) {
            const uint32_t An = sb + SM_A + (uint32_t)((j2 + 3) & 3) * 16384;
            STS128(An + asts0, ar);
            STS128(An + asts1, ar + 4);
            CP_WAIT0();
        }
        __syncthreads();      // single barrier per 2-block stage
    }

    // ---- epilogue: smem transpose to [oc][m], coalesced stores ----
    const int eg = lane >> 2, ee = lane & 3;
    #pragma unroll 1
    for (int p = 0; p < 2; p++) {
        if ((n0 >> 7) == p) {
            #pragma unroll
            for (int mi = 0; mi < 2; mi++)
                #pragma unroll
                for (int nj = 0; nj < 8; nj++) {
                    int ocl = (n0 & 127) + nj * 8 + 2 * ee;
                    int mm  = m0 + mi * 16 + eg;
                    smf[ocl * EPI_LD + mm]           = acc[mi][nj][0];
                    smf[(ocl + 1) * EPI_LD + mm]     = acc[mi][nj][1];
                    smf[ocl * EPI_LD + mm + 8]       = acc[mi][nj][2];
                    smf[(ocl + 1) * EPI_LD + mm + 8] = acc[mi][nj][3];
                }
        }
        __syncthreads();
        #pragma unroll 4
        for (int i = 0; i < 32; i++) {
            int idx = i * NTHR + tid;
            int mm = idx & 127, ocl = idx >> 7;
            int ow = mm & 63, oh = oh0 + (mm >> 6);
            if (ow < 62)
                out[((size_t)n * 256 + p * 128 + ocl) * 3844 + (size_t)oh * 62 + ow]
                    = smf[ocl * EPI_LD + mm];
        }
        __syncthreads();
    }
}

extern "C" void kernel_launch(void* const* d_in, const int* in_sizes, int n_in,
                              void* d_out, int out_size)
{
    const float* in = (const float*)d_in[0];   // [32,128,64,64]
    const float* wt = (const float*)d_in[1];   // [256,128,3,3]
    float* out = (float*)d_out;                // [32,256,62,62]

    // prepass: convert input + weights to tf32 bit patterns
    cvt_in_kernel<<<2048, 256>>>(reinterpret_cast<const float4*>(in));
    cvt_wt_kernel<<<288, 256>>>(reinterpret_cast<const float4*>(wt));

    cudaFuncSetAttribute(conv2d_tf32_mmasync,
                         cudaFuncAttributeMaxDynamicSharedMemorySize, SM_TOT);
    dim3 grid(31, 32);
    conv2d_tf32_mmasync<<<grid, NTHR, SM_TOT>>>(out);
}

// round 11
// speedup vs baseline: 1.5660x; 1.0533x over previous
#include <cuda_runtime.h>
#include <cstdint>

#define NTHR 512
#define KTOT 1152
#define NBLK 36          // K blocks of 32

// smem layout (bytes) — 4-deep buffers, swizzled 128B rows
#define SM_A   0                       // 4 x (128 rows * 128B) = 64KB
#define SM_B   65536                   // 4 x (256 rows * 128B) = 128KB
#define SM_OFF 196608                  // 1152 int offsets
#define SM_TOT 201216
#define EPI_LD 132                     // epilogue [256 oc][132 m] floats = 135KB

// ---- tf32-preconverted weights (device global scratch) ----
__device__ float g_wt_tf[256u * KTOT];              // 1.18 MB

__device__ __forceinline__ uint32_t s2u(const void* p) {
    uint32_t a;
    asm("{ .reg .u64 t; cvta.to.shared.u64 t, %1; cvt.u32.u64 %0, t; }" : "=r"(a) : "l"(p));
    return a;
}

__device__ __forceinline__ void ldsm4(uint32_t* r, uint32_t addr) {
    asm volatile("ldmatrix.sync.aligned.m8n8.x4.shared.b16 {%0,%1,%2,%3}, [%4];"
        : "=r"(r[0]), "=r"(r[1]), "=r"(r[2]), "=r"(r[3]) : "r"(addr));
}

__device__ __forceinline__ float f2tf(float f) {
    uint32_t o;
    asm("cvt.rna.tf32.f32 %0, %1;" : "=r"(o) : "f"(f));
    return __uint_as_float(o);
}

__device__ __forceinline__ void mma8(float* d, const uint32_t* a, const uint32_t* b) {
    asm volatile("mma.sync.aligned.m16n8k8.row.col.f32.tf32.tf32.f32 "
        "{%0,%1,%2,%3}, {%4,%5,%6,%7}, {%8,%9}, {%0,%1,%2,%3};"
        : "+f"(d[0]), "+f"(d[1]), "+f"(d[2]), "+f"(d[3])
        : "r"(a[0]), "r"(a[1]), "r"(a[2]), "r"(a[3]), "r"(b[0]), "r"(b[1]));
}

#define CP16(dst, src) \
    asm volatile("cp.async.cg.shared.global [%0], [%1], 16;" :: "r"(dst), "l"(src) : "memory")
#define CP_COMMIT()  asm volatile("cp.async.commit_group;" ::: "memory")
#define CP_WAIT0()   asm volatile("cp.async.wait_group 0;" ::: "memory")
#define STS128(a, r) \
    asm volatile("st.shared.v4.b32 [%0], {%1,%2,%3,%4};" :: "r"(a), \
        "r"(__float_as_uint((r)[0])), "r"(__float_as_uint((r)[1])), \
        "r"(__float_as_uint((r)[2])), "r"(__float_as_uint((r)[3])) : "memory")

// ---- prepass: weights f32 -> tf32 bit patterns ----
__global__ __launch_bounds__(256) void cvt_wt_kernel(const float4* __restrict__ src) {
    float4* dst = reinterpret_cast<float4*>(g_wt_tf);
    const int n4 = (256 * KTOT) / 4;
    for (int i = blockIdx.x * blockDim.x + threadIdx.x; i < n4; i += gridDim.x * blockDim.x) {
        float4 v = src[i];
        v.x = f2tf(v.x); v.y = f2tf(v.y); v.z = f2tf(v.z); v.w = f2tf(v.w);
        dst[i] = v;
    }
}

__global__ __launch_bounds__(NTHR, 1)
void conv2d_tf32_mmasync(const float* __restrict__ in, float* __restrict__ out)
{
    extern __shared__ char smem[];
    const uint32_t sb = s2u(smem);
    float* smf = (float*)smem;
    int* offs = (int*)(smem + SM_OFF);

    const int tid = threadIdx.x;
    const int wid = tid >> 5, lane = tid & 31;
    const int n   = blockIdx.y;
    const int oh0 = blockIdx.x * 2;

    // k -> input offset table (floats): ic*4096 + kh*64 + kw
    for (int k = tid; k < KTOT; k += NTHR) {
        int ic = k / 9, t9 = k - ic * 9;
        int kh = t9 / 3, kw = t9 - kh * 3;
        offs[k] = ic * 4096 + kh * 64 + kw;
    }

    // ---- A staging: thread = (m = tid&127, k-octet aq = tid>>7) ----
    const float* in_n = in + (size_t)n * 128 * 64 * 64;
    const float* wtp  = g_wt_tf;
    const int am = tid & 127, aq = tid >> 7;          // aq in 0..3
    const int aow = am & 63;
    const float* abase = in_n + (size_t)(oh0 + (am >> 6)) * 64 + (aow < 62 ? aow : 0);
    const uint32_t axm_st  = (uint32_t)(am & 7) << 4;
    const uint32_t asts0 = (uint32_t)am * 128 + (((uint32_t)aq * 32)      ^ axm_st);
    const uint32_t asts1 = (uint32_t)am * 128 + (((uint32_t)aq * 32 + 16) ^ axm_st);

    // ---- B staging: thread = (oc-block bocb = tid>>3, quad bq = tid&7) ----
    const int bq = tid & 7, bocb = tid >> 3;          // bocb in 0..63
    const uint32_t bstcol = ((uint32_t)bq * 16) ^ ((uint32_t)(bocb & 7) << 4);

    // ---- warp tiling: 4x4 grid, warp tile m32 x n64 ----
    const int m0 = (wid & 3) * 32, n0 = (wid >> 2) * 64;
    const int T = lane >> 3, rowin = lane & 7;
    const uint32_t acol = (uint32_t)(T >> 1) << 4;
    const uint32_t bcol = (uint32_t)(T & 1) << 4;
    uint32_t arow[2], axm[2], brow[4], bxm[4];
    #pragma unroll
    for (int mi = 0; mi < 2; mi++) {
        int r = m0 + mi * 16 + ((T & 1) << 3) + rowin;
        arow[mi] = (uint32_t)r * 128; axm[mi] = (uint32_t)(r & 7) << 4;
    }
    #pragma unroll
    for (int nb = 0; nb < 4; nb++) {
        int r = n0 + nb * 16 + ((T >> 1) << 3) + rowin;
        brow[nb] = (uint32_t)r * 128; bxm[nb] = (uint32_t)(r & 7) << 4;
    }

    float acc[2][8][4];
    #pragma unroll
    for (int i = 0; i < 2; i++)
        #pragma unroll
        for (int j = 0; j < 8; j++)
            #pragma unroll
            for (int v = 0; v < 4; v++) acc[i][j][v] = 0.0f;

    __syncthreads();   // offs table ready

    float ar[8];
    // ---- prologue: stage blocks 0 and 1 into buffers 0,1 ----
    #pragma unroll
    for (int blk = 0; blk < 2; blk++) {
        const int kb = blk * 32 + aq * 8;
        #pragma unroll
        for (int j = 0; j < 8; j++) ar[j] = f2tf(abase[offs[kb + j]]);
        const uint32_t Bs = sb + SM_B + (uint32_t)blk * 32768;
        #pragma unroll
        for (int j = 0; j < 4; j++) {
            int oc = j * 64 + bocb;
            CP16(Bs + (uint32_t)oc * 128 + bstcol,
                 wtp + (size_t)oc * KTOT + blk * 32 + bq * 4);
        }
        const uint32_t As = sb + SM_A + (uint32_t)blk * 16384;
        STS128(As + asts0, ar);
        STS128(As + asts1, ar + 4);
    }
    CP_COMMIT();
    CP_WAIT0();
    __syncthreads();

    #pragma unroll 1
    for (int j2 = 0; j2 < NBLK; j2 += 2) {
        const bool more = (j2 + 2 < NBLK);

        // issue B cp.async for blocks j2+2, j2+3 and A LDG for block j2+2
        if (more) {
            #pragma unroll
            for (int blk = 0; blk < 2; blk++) {
                const int jb = j2 + 2 + blk;
                const uint32_t Bs = sb + SM_B + (uint32_t)(jb & 3) * 32768;
                #pragma unroll
                for (int j = 0; j < 4; j++) {
                    int oc = j * 64 + bocb;
                    CP16(Bs + (uint32_t)oc * 128 + bstcol,
                         wtp + (size_t)oc * KTOT + jb * 32 + bq * 4);
                }
            }
            CP_COMMIT();
            const int kb = (j2 + 2) * 32 + aq * 8;
            #pragma unroll
            for (int j = 0; j < 8; j++) ar[j] = abase[offs[kb + j]];
        }

        // ---- compute block j2 ----
        {
            const uint32_t As = sb + SM_A + (uint32_t)(j2 & 3) * 16384;
            const uint32_t Bs = sb + SM_B + (uint32_t)(j2 & 3) * 32768;
            #pragma unroll
            for (int s = 0; s < 4; s++) {
                uint32_t a[2][4], b[4][4];
                #pragma unroll
                for (int mi = 0; mi < 2; mi++)
                    ldsm4(a[mi], As + arow[mi] + ((acol | ((uint32_t)s << 5)) ^ axm[mi]));
                #pragma unroll
                for (int nb = 0; nb < 4; nb++)
                    ldsm4(b[nb], Bs + brow[nb] + ((bcol | ((uint32_t)s << 5)) ^ bxm[nb]));
                #pragma unroll
                for (int mi = 0; mi < 2; mi++)
                    #pragma unroll
                    for (int nb = 0; nb < 4; nb++) {
                        mma8(acc[mi][2 * nb],     a[mi], &b[nb][0]);
                        mma8(acc[mi][2 * nb + 1], a[mi], &b[nb][2]);
                    }
            }
        }

        // cvt + store A block j2+2, load A block j2+3
        if (more) {
            #pragma unroll
            for (int j = 0; j < 8; j++) ar[j] = f2tf(ar[j]);
            const uint32_t An = sb + SM_A + (uint32_t)((j2 + 2) & 3) * 16384;
            STS128(An + asts0, ar);
            STS128(An + asts1, ar + 4);
            const int kb = (j2 + 3) * 32 + aq * 8;
            #pragma unroll
            for (int j = 0; j < 8; j++) ar[j] = abase[offs[kb + j]];
        }

        // ---- compute block j2+1 ----
        {
            const uint32_t As = sb + SM_A + (uint32_t)((j2 + 1) & 3) * 16384;
            const uint32_t Bs = sb + SM_B + (uint32_t)((j2 + 1) & 3) * 32768;
            #pragma unroll
            for (int s = 0; s < 4; s++) {
                uint32_t a[2][4], b[4][4];
                #pragma unroll
                for (int mi = 0; mi < 2; mi++)
                    ldsm4(a[mi], As + arow[mi] + ((acol | ((uint32_t)s << 5)) ^ axm[mi]));
                #pragma unroll
                for (int nb = 0; nb < 4; nb++)
                    ldsm4(b[nb], Bs + brow[nb] + ((bcol | ((uint32_t)s << 5)) ^ bxm[nb]));
                #pragma unroll
                for (int mi = 0; mi < 2; mi++)
                    #pragma unroll
                    for (int nb = 0; nb < 4; nb++) {
                        mma8(acc[mi][2 * nb],     a[mi], &b[nb][0]);
                        mma8(acc[mi][2 * nb + 1], a[mi], &b[nb][2]);
                    }
            }
        }

        if (more) {
            #pragma unroll
            for (int j = 0; j < 8; j++) ar[j] = f2tf(ar[j]);
            const uint32_t An = sb + SM_A + (uint32_t)((j2 + 3) & 3) * 16384;
            STS128(An + asts0, ar);
            STS128(An + asts1, ar + 4);
            CP_WAIT0();
        }
        __syncthreads();      // single barrier per 2-block stage
    }

    // ---- epilogue: full 256-oc transpose in smem (135KB), 1 barrier ----
    const int eg = lane >> 2, ee = lane & 3;
    #pragma unroll
    for (int mi = 0; mi < 2; mi++)
        #pragma unroll
        for (int nj = 0; nj < 8; nj++) {
            int oc  = n0 + nj * 8 + 2 * ee;
            int mm  = m0 + mi * 16 + eg;
            smf[oc * EPI_LD + mm]           = acc[mi][nj][0];
            smf[(oc + 1) * EPI_LD + mm]     = acc[mi][nj][1];
            smf[oc * EPI_LD + mm + 8]       = acc[mi][nj][2];
            smf[(oc + 1) * EPI_LD + mm + 8] = acc[mi][nj][3];
        }
    __syncthreads();
    #pragma unroll 4
    for (int i = 0; i < 64; i++) {
        int idx = i * NTHR + tid;
        int mm = idx & 127, oc = idx >> 7;
        int ow = mm & 63, oh = oh0 + (mm >> 6);
        if (ow < 62)
            out[((size_t)n * 256 + oc) * 3844 + (size_t)oh * 62 + ow]
                = smf[oc * EPI_LD + mm];
    }
}

extern "C" void kernel_launch(void* const* d_in, const int* in_sizes, int n_in,
                              void* d_out, int out_size)
{
    const float* in = (const float*)d_in[0];   // [32,128,64,64]
    const float* wt = (const float*)d_in[1];   // [256,128,3,3]
    float* out = (float*)d_out;                // [32,256,62,62]

    // prepass: convert weights to tf32 bit patterns (input cvt fused into main)
    cvt_wt_kernel<<<288, 256>>>(reinterpret_cast<const float4*>(wt));

    cudaFuncSetAttribute(conv2d_tf32_mmasync,
                         cudaFuncAttributeMaxDynamicSharedMemorySize, SM_TOT);
    dim3 grid(31, 32);
    conv2d_tf32_mmasync<<<grid, NTHR, SM_TOT>>>(in, out);
}